// round 1
// baseline (speedup 1.0000x reference)
#include <cuda_runtime.h>

#define EPS_ 0.001f

// Problem constants
#define NB   16
#define CIN  64
#define CO   64
#define TT   64
#define VV   384
#define PP   (TT*VV)          // 24576 positions per (n, channel)
#define XP_ELEMS  (NB*CO*PP)  // 25165824  (x' scratch, also size of "out")
#define CS_ELEMS  (NB*CO*VV)  // 393216    (column sums)

// Scratch (no cudaMalloc allowed)
__device__ float g_xp[XP_ELEMS];
__device__ float g_colsum[CS_ELEMS];

// ---------------------------------------------------------------------------
// K0: zero the column-sum accumulator
// ---------------------------------------------------------------------------
__global__ void zero_colsum_kernel() {
    int i = blockIdx.x * blockDim.x + threadIdx.x;
    if (i < CS_ELEMS) g_colsum[i] = 0.0f;
}

// ---------------------------------------------------------------------------
// K1: x'[n,o,p] = sum_c conv_w[o,c] * x[n,c,p] + conv_b[o]
// Per-block: one n, 64 output channels x 64 positions.
// ---------------------------------------------------------------------------
__global__ __launch_bounds__(256) void conv_kernel(const float* __restrict__ x,
                                                   const float* __restrict__ w,
                                                   const float* __restrict__ b) {
    __shared__ float sW[64 * 65];   // padded rows to kill bank conflicts
    __shared__ float sX[64 * 64];
    const int n   = blockIdx.y;
    const int p0  = blockIdx.x * 64;
    const int tid = threadIdx.x;

    for (int i = tid; i < 4096; i += 256)
        sW[(i >> 6) * 65 + (i & 63)] = w[i];

    const float* xb = x + n * CIN * PP;
    #pragma unroll
    for (int r = 0; r < 16; r++) {
        int idx = tid + 256 * r;
        int c = idx >> 6, p = idx & 63;
        sX[c * 64 + p] = xb[c * PP + p0 + p];
    }
    __syncthreads();

    const int ob = tid >> 4;   // 0..15
    const int px = tid & 15;   // 0..15
    float acc[4][4];
    #pragma unroll
    for (int i = 0; i < 4; i++)
        #pragma unroll
        for (int j = 0; j < 4; j++) acc[i][j] = 0.0f;

    #pragma unroll 8
    for (int c = 0; c < 64; c++) {
        float xv[4], wv[4];
        #pragma unroll
        for (int j = 0; j < 4; j++) xv[j] = sX[c * 64 + px + 16 * j];
        #pragma unroll
        for (int i = 0; i < 4; i++) wv[i] = sW[(ob + 16 * i) * 65 + c];
        #pragma unroll
        for (int i = 0; i < 4; i++)
            #pragma unroll
            for (int j = 0; j < 4; j++) acc[i][j] += wv[i] * xv[j];
    }

    #pragma unroll
    for (int i = 0; i < 4; i++) {
        int o = ob + 16 * i;
        float bo = __ldg(&b[o]);
        float* op = g_xp + (n * CO + o) * PP + p0;
        #pragma unroll
        for (int j = 0; j < 4; j++) op[px + 16 * j] = acc[i][j] + bo;
    }
}

// ---------------------------------------------------------------------------
// K2: MLP 7->16->32->64 (ReLU each stage), mask multiply, write Am
// (unnormalized An) into the An region of d_out, and accumulate column sums.
// Block = one n, tile of 16 v x 32 w = 512 positions. Staged GEMMs in smem.
// ---------------------------------------------------------------------------
#define S2_A   0          // sA  [8][512]
#define S2_H1  4096       // sH1 [16][512]
#define S2_H2  12288      // sH2 [32][512]
#define S2_W1  28672      // 112
#define S2_B1  28784      // 16
#define S2_W2  28800      // 512
#define S2_B2  29312      // 32
#define S2_W3  29344      // 2048
#define S2_B3  31392      // 64
#define S2_FLOATS 31456
#define S2_BYTES  (S2_FLOATS * 4)

__global__ __launch_bounds__(256, 1) void mlp_kernel(
    const float* __restrict__ A,
    const float* __restrict__ w1, const float* __restrict__ b1,
    const float* __restrict__ w2, const float* __restrict__ b2,
    const float* __restrict__ w3, const float* __restrict__ b3,
    float* __restrict__ Am)
{
    extern __shared__ float s[];
    float* sA  = s + S2_A;
    float* sH1 = s + S2_H1;
    float* sH2 = s + S2_H2;
    float* sW1 = s + S2_W1; float* sB1 = s + S2_B1;
    float* sW2 = s + S2_W2; float* sB2 = s + S2_B2;
    float* sW3 = s + S2_W3; float* sB3 = s + S2_B3;

    const int tid = threadIdx.x;
    const int w0  = blockIdx.x * 32;
    const int v0  = blockIdx.y * 16;
    const int n   = blockIdx.z;

    // weights -> smem
    if (tid < 112) sW1[tid] = w1[tid];
    if (tid < 16)  sB1[tid] = b1[tid];
    for (int i = tid; i < 512; i += 256)  sW2[i] = w2[i];
    if (tid < 32)  sB2[tid] = b2[tid];
    for (int i = tid; i < 2048; i += 256) sW3[i] = w3[i];
    if (tid < 64)  sB3[tid] = b3[tid];

    // A tile: 8 channels x 16 v x 32 w (channel 7 = mask)
    {
        const int w   = tid & 31;
        const int sub = tid >> 5;   // 0..7
        const float* Ab = A + n * 8 * VV * VV;
        #pragma unroll
        for (int k = 0; k < 8; k++)
            #pragma unroll
            for (int vi = 0; vi < 2; vi++) {
                int v = sub + vi * 8;
                sA[k * 512 + v * 32 + w] = Ab[(k * VV + v0 + v) * VV + w0 + w];
            }
    }
    __syncthreads();

    // ---- stage 1: H1[16][512] ----
    #pragma unroll
    for (int jj = 0; jj < 2; jj++) {
        int p = tid + jj * 256;
        float av[7];
        #pragma unroll
        for (int k = 0; k < 7; k++) av[k] = sA[k * 512 + p];
        #pragma unroll
        for (int c = 0; c < 16; c++) {
            float h = sB1[c];
            #pragma unroll
            for (int k = 0; k < 7; k++) h += sW1[c * 7 + k] * av[k];
            sH1[c * 512 + p] = fmaxf(h, 0.0f);
        }
    }
    __syncthreads();

    // ---- stage 2: H2[32][512] ----
    {
        const int pg = tid & 63;
        const int cb = tid >> 6;   // 0..3 -> 8 channels each
        float acc[8][8];
        #pragma unroll
        for (int i = 0; i < 8; i++) {
            float bb = sB2[cb * 8 + i];
            #pragma unroll
            for (int j = 0; j < 8; j++) acc[i][j] = bb;
        }
        #pragma unroll
        for (int k = 0; k < 16; k++) {
            float hv[8], wv[8];
            #pragma unroll
            for (int j = 0; j < 8; j++) hv[j] = sH1[k * 512 + pg + 64 * j];
            #pragma unroll
            for (int i = 0; i < 8; i++) wv[i] = sW2[(cb * 8 + i) * 16 + k];
            #pragma unroll
            for (int i = 0; i < 8; i++)
                #pragma unroll
                for (int j = 0; j < 8; j++) acc[i][j] += wv[i] * hv[j];
        }
        #pragma unroll
        for (int i = 0; i < 8; i++)
            #pragma unroll
            for (int j = 0; j < 8; j++)
                sH2[(cb * 8 + i) * 512 + pg + 64 * j] = fmaxf(acc[i][j], 0.0f);
    }
    __syncthreads();

    // ---- stage 3: H3[64][512] -> relu -> mask -> Am + colsum ----
    {
        const int w  = tid & 31;
        const int cb = tid >> 5;   // 0..7 -> 8 channels each, thread owns 16 v
        float acc[8][16];
        #pragma unroll
        for (int i = 0; i < 8; i++) {
            float bb = sB3[cb * 8 + i];
            #pragma unroll
            for (int v = 0; v < 16; v++) acc[i][v] = bb;
        }
        #pragma unroll 4
        for (int k = 0; k < 32; k++) {
            float hv[16], wv[8];
            #pragma unroll
            for (int v = 0; v < 16; v++) hv[v] = sH2[k * 512 + v * 32 + w];
            #pragma unroll
            for (int i = 0; i < 8; i++) wv[i] = sW3[(cb * 8 + i) * 32 + k];
            #pragma unroll
            for (int i = 0; i < 8; i++)
                #pragma unroll
                for (int v = 0; v < 16; v++) acc[i][v] += wv[i] * hv[v];
        }
        float cs[8];
        #pragma unroll
        for (int i = 0; i < 8; i++) cs[i] = 0.0f;
        #pragma unroll
        for (int v = 0; v < 16; v++) {
            float m = sA[7 * 512 + v * 32 + w];
            #pragma unroll
            for (int i = 0; i < 8; i++) {
                float am = fmaxf(acc[i][v], 0.0f) * m;
                Am[((n * CO + cb * 8 + i) * VV + (v0 + v)) * VV + w0 + w] = am;
                cs[i] += am;
            }
        }
        #pragma unroll
        for (int i = 0; i < 8; i++)
            atomicAdd(&g_colsum[(n * CO + cb * 8 + i) * VV + w0 + w], cs[i]);
    }
}

// ---------------------------------------------------------------------------
// K3: per (n,c): out[t,w] = Dl[w] * sum_v x'[t,v] * Am[v,w],
// and normalize An = Am * Dl[w] IN PLACE while streaming Am tiles.
// Block = (n, c, 128-wide w tile). Full x' row (64x384) in smem.
// ---------------------------------------------------------------------------
#define S3_X   0         // 24576 floats
#define S3_AM  24576     // 32*128 = 4096
#define S3_DL  28672     // 128
#define S3_FLOATS 28800
#define S3_BYTES  (S3_FLOATS * 4)

__global__ __launch_bounds__(256, 1) void out_kernel(float* __restrict__ out,
                                                     float* __restrict__ An)
{
    extern __shared__ float s[];
    float* sX  = s + S3_X;
    float* sAm = s + S3_AM;
    float* sDl = s + S3_DL;

    const int tid = threadIdx.x;
    const int w0  = blockIdx.x * 128;
    const int c   = blockIdx.y;
    const int n   = blockIdx.z;
    const int nc  = n * CO + c;

    // x'[64][384] -> smem (float4)
    const float4* xb4 = (const float4*)(g_xp + nc * PP);
    float4* sX4 = (float4*)sX;
    #pragma unroll
    for (int r = 0; r < 24; r++) sX4[tid + r * 256] = xb4[tid + r * 256];

    if (tid < 128) {
        float csv = g_colsum[nc * VV + w0 + tid];
        sDl[tid] = 1.0f / (csv + EPS_);
    }
    __syncthreads();

    const int tx = tid & 31;   // 4 w each (tx + 32j)
    const int ty = tid >> 5;   // 8 t each (ty + 8i)
    float acc[8][4];
    #pragma unroll
    for (int i = 0; i < 8; i++)
        #pragma unroll
        for (int j = 0; j < 4; j++) acc[i][j] = 0.0f;

    float* Anb = An + nc * VV * VV + w0;

    for (int kc = 0; kc < 12; kc++) {
        const int vbase = kc * 32;
        // stream Am chunk [32 x 128]; write normalized An back in place
        #pragma unroll
        for (int r = 0; r < 4; r++) {
            int lin = tid + r * 256;       // float4 index 0..1023
            int row = lin >> 5;            // 0..31
            int c4  = lin & 31;            // float4 column
            float4* gp = (float4*)(Anb + (vbase + row) * VV) + c4;
            float4 a4 = *gp;
            ((float4*)sAm)[row * 32 + c4] = a4;
            float4 o4;
            o4.x = a4.x * sDl[c4 * 4 + 0];
            o4.y = a4.y * sDl[c4 * 4 + 1];
            o4.z = a4.z * sDl[c4 * 4 + 2];
            o4.w = a4.w * sDl[c4 * 4 + 3];
            *gp = o4;
        }
        __syncthreads();
        #pragma unroll 8
        for (int v = 0; v < 32; v++) {
            float xv[8], av[4];
            #pragma unroll
            for (int i = 0; i < 8; i++) xv[i] = sX[(ty + 8 * i) * VV + vbase + v];
            #pragma unroll
            for (int j = 0; j < 4; j++) av[j] = sAm[v * 128 + tx + 32 * j];
            #pragma unroll
            for (int i = 0; i < 8; i++)
                #pragma unroll
                for (int j = 0; j < 4; j++) acc[i][j] += xv[i] * av[j];
        }
        __syncthreads();
    }

    float dl[4];
    #pragma unroll
    for (int j = 0; j < 4; j++) dl[j] = sDl[tx + 32 * j];
    float* ob = out + nc * PP + w0;
    #pragma unroll
    for (int i = 0; i < 8; i++) {
        int t = ty + 8 * i;
        #pragma unroll
        for (int j = 0; j < 4; j++)
            ob[t * VV + tx + 32 * j] = acc[i][j] * dl[j];
    }
}

// ---------------------------------------------------------------------------
extern "C" void kernel_launch(void* const* d_in, const int* in_sizes, int n_in,
                              void* d_out, int out_size) {
    const float* x      = (const float*)d_in[0];
    const float* A      = (const float*)d_in[1];
    const float* conv_w = (const float*)d_in[2];
    const float* conv_b = (const float*)d_in[3];
    const float* w1     = (const float*)d_in[4];
    const float* b1     = (const float*)d_in[5];
    const float* w2     = (const float*)d_in[6];
    const float* b2     = (const float*)d_in[7];
    const float* w3     = (const float*)d_in[8];
    const float* b3     = (const float*)d_in[9];

    float* out = (float*)d_out;
    float* An  = out + XP_ELEMS;   // tuple layout: out first, then An

    cudaFuncSetAttribute(mlp_kernel, cudaFuncAttributeMaxDynamicSharedMemorySize, S2_BYTES);
    cudaFuncSetAttribute(out_kernel, cudaFuncAttributeMaxDynamicSharedMemorySize, S3_BYTES);

    zero_colsum_kernel<<<(CS_ELEMS + 255) / 256, 256>>>();
    conv_kernel<<<dim3(PP / 64, NB), 256>>>(x, conv_w, conv_b);
    mlp_kernel<<<dim3(VV / 32, VV / 16, NB), 256, S2_BYTES>>>(A, w1, b1, w2, b2, w3, b3, An);
    out_kernel<<<dim3(VV / 128, CO, NB), 256, S3_BYTES>>>(out, An);
}

// round 2
// speedup vs baseline: 1.2629x; 1.2629x over previous
#include <cuda_runtime.h>

#define EPS_ 0.001f

// Problem constants
#define NB   16
#define CIN  64
#define CO   64
#define TT   64
#define VV   384
#define PP   (TT*VV)          // 24576 positions per (n, channel)
#define XP_ELEMS  (NB*CO*PP)  // 25165824
#define CS_ELEMS  (NB*CO*VV)  // 393216

typedef unsigned long long ull;

// Scratch (no cudaMalloc allowed)
__device__ float g_xp[XP_ELEMS];
__device__ float g_colsum[CS_ELEMS];

// ---------------------------------------------------------------------------
// packed f32x2 helpers (Blackwell FFMA2 path — only reachable via PTX)
// ---------------------------------------------------------------------------
__device__ __forceinline__ ull pack2(float lo, float hi) {
    ull r; asm("mov.b64 %0, {%1, %2};" : "=l"(r) : "f"(lo), "f"(hi)); return r;
}
__device__ __forceinline__ ull splat2(float v) {
    ull r; asm("mov.b64 %0, {%1, %1};" : "=l"(r) : "f"(v)); return r;
}
__device__ __forceinline__ void unpack2(ull p, float& lo, float& hi) {
    asm("mov.b64 {%0, %1}, %2;" : "=f"(lo), "=f"(hi) : "l"(p));
}
__device__ __forceinline__ ull fma2(ull a, ull b, ull c) {
    ull d; asm("fma.rn.f32x2 %0, %1, %2, %3;" : "=l"(d) : "l"(a), "l"(b), "l"(c)); return d;
}

// ---------------------------------------------------------------------------
// K0: zero the column-sum accumulator
// ---------------------------------------------------------------------------
__global__ void zero_colsum_kernel() {
    int i = blockIdx.x * blockDim.x + threadIdx.x;
    if (i < CS_ELEMS) g_colsum[i] = 0.0f;
}

// ---------------------------------------------------------------------------
// K1: x'[n,o,p] = sum_c conv_w[o,c] * x[n,c,p] + conv_b[o]
// ---------------------------------------------------------------------------
__global__ __launch_bounds__(256) void conv_kernel(const float* __restrict__ x,
                                                   const float* __restrict__ w,
                                                   const float* __restrict__ b) {
    __shared__ float sW[64 * 65];
    __shared__ float sX[64 * 64];
    const int n   = blockIdx.y;
    const int p0  = blockIdx.x * 64;
    const int tid = threadIdx.x;

    for (int i = tid; i < 4096; i += 256)
        sW[(i >> 6) * 65 + (i & 63)] = w[i];

    const float* xb = x + n * CIN * PP;
    #pragma unroll
    for (int r = 0; r < 16; r++) {
        int idx = tid + 256 * r;
        int c = idx >> 6, p = idx & 63;
        sX[c * 64 + p] = xb[c * PP + p0 + p];
    }
    __syncthreads();

    const int ob = tid >> 4;
    const int px = tid & 15;
    float acc[4][4];
    #pragma unroll
    for (int i = 0; i < 4; i++)
        #pragma unroll
        for (int j = 0; j < 4; j++) acc[i][j] = 0.0f;

    #pragma unroll 8
    for (int c = 0; c < 64; c++) {
        float xv[4], wv[4];
        #pragma unroll
        for (int j = 0; j < 4; j++) xv[j] = sX[c * 64 + px + 16 * j];
        #pragma unroll
        for (int i = 0; i < 4; i++) wv[i] = sW[(ob + 16 * i) * 65 + c];
        #pragma unroll
        for (int i = 0; i < 4; i++)
            #pragma unroll
            for (int j = 0; j < 4; j++) acc[i][j] += wv[i] * xv[j];
    }

    #pragma unroll
    for (int i = 0; i < 4; i++) {
        int o = ob + 16 * i;
        float bo = __ldg(&b[o]);
        float* op = g_xp + (n * CO + o) * PP + p0;
        #pragma unroll
        for (int j = 0; j < 4; j++) op[px + 16 * j] = acc[i][j] + bo;
    }
}

// ---------------------------------------------------------------------------
// K2: MLP 7->16->32->64 (ReLU each stage), mask multiply -> Am + colsum.
// Fused stage1+2 in registers (no sH1), f32x2 packed math, 2 blocks/SM.
// Block = one n, tile of 16 v x 32 w = 512 positions.
// ---------------------------------------------------------------------------
#define S2_A    0                 // sA  [8][512]          4096
#define S2_H2   4096              // sH2 [32][512]         16384
#define S2_W1T  20480             // w1t [7][16] (pad 128) 128
#define S2_B1   20608             // 16
#define S2_W2T  20624             // w2t [16][32]          512
#define S2_B2   21136             // 32
#define S2_W3T  21168             // w3t [32][64]          2048
#define S2_B3   23216             // 64
#define S2_FLOATS 23280
#define S2_BYTES  (S2_FLOATS * 4)

__global__ __launch_bounds__(256, 2) void mlp_kernel(
    const float* __restrict__ A,
    const float* __restrict__ w1, const float* __restrict__ b1,
    const float* __restrict__ w2, const float* __restrict__ b2,
    const float* __restrict__ w3, const float* __restrict__ b3,
    float* __restrict__ Am)
{
    extern __shared__ float s[];
    float* sA   = s + S2_A;
    float* sH2  = s + S2_H2;
    float* sW1t = s + S2_W1T; float* sB1 = s + S2_B1;
    float* sW2t = s + S2_W2T; float* sB2 = s + S2_B2;
    float* sW3t = s + S2_W3T; float* sB3 = s + S2_B3;

    const int tid = threadIdx.x;
    const int w0  = blockIdx.x * 32;
    const int v0  = blockIdx.y * 16;
    const int n   = blockIdx.z;

    // weights -> smem (transposed so channel pairs are contiguous)
    if (tid < 112) { int c = tid / 7, k = tid % 7; sW1t[k * 16 + c] = w1[tid]; }
    if (tid < 16)  sB1[tid] = b1[tid];
    for (int i = tid; i < 512; i += 256)  { int c = i >> 4, k = i & 15; sW2t[k * 32 + c] = w2[i]; }
    if (tid < 32)  sB2[tid] = b2[tid];
    for (int i = tid; i < 2048; i += 256) { int c = i >> 5, k = i & 31; sW3t[k * 64 + c] = w3[i]; }
    if (tid < 64)  sB3[tid] = b3[tid];

    // A tile: 8 channels x 16 v x 32 w (channel 7 = mask)
    {
        const int w   = tid & 31;
        const int sub = tid >> 5;
        const float* Ab = A + n * 8 * VV * VV;
        #pragma unroll
        for (int k = 0; k < 8; k++)
            #pragma unroll
            for (int vi = 0; vi < 2; vi++) {
                int v = sub + vi * 8;
                sA[k * 512 + v * 32 + w] = Ab[(k * VV + v0 + v) * VV + w0 + w];
            }
    }
    __syncthreads();

    // ---- fused stage 1+2: per position, H1 and H2 in registers ----
    #pragma unroll
    for (int jj = 0; jj < 2; jj++) {
        const int p = tid + jj * 256;
        float av[7];
        #pragma unroll
        for (int k = 0; k < 7; k++) av[k] = sA[k * 512 + p];

        ull h1p[8];
        #pragma unroll
        for (int ci = 0; ci < 8; ci++) h1p[ci] = *(const ull*)&sB1[2 * ci];
        #pragma unroll
        for (int k = 0; k < 7; k++) {
            ull sv = splat2(av[k]);
            #pragma unroll
            for (int ci = 0; ci < 8; ci++)
                h1p[ci] = fma2(sv, *(const ull*)&sW1t[k * 16 + 2 * ci], h1p[ci]);
        }
        float h1[16];
        #pragma unroll
        for (int ci = 0; ci < 8; ci++) {
            float lo, hi; unpack2(h1p[ci], lo, hi);
            h1[2 * ci]     = fmaxf(lo, 0.0f);
            h1[2 * ci + 1] = fmaxf(hi, 0.0f);
        }

        ull h2p[16];
        #pragma unroll
        for (int ci = 0; ci < 16; ci++) h2p[ci] = *(const ull*)&sB2[2 * ci];
        #pragma unroll
        for (int k = 0; k < 16; k++) {
            ull sv = splat2(h1[k]);
            #pragma unroll
            for (int ci = 0; ci < 16; ci++)
                h2p[ci] = fma2(sv, *(const ull*)&sW2t[k * 32 + 2 * ci], h2p[ci]);
        }
        #pragma unroll
        for (int ci = 0; ci < 16; ci++) {
            float lo, hi; unpack2(h2p[ci], lo, hi);
            sH2[(2 * ci) * 512 + p]     = fmaxf(lo, 0.0f);
            sH2[(2 * ci + 1) * 512 + p] = fmaxf(hi, 0.0f);
        }
    }
    __syncthreads();

    // ---- stage 3: 32 -> 64, relu, mask, Am write + colsum ----
    {
        const int w  = tid & 31;
        const int cb = tid >> 5;       // 8 groups of 8 channels (4 pairs)
        float cs[8];
        #pragma unroll
        for (int i = 0; i < 8; i++) cs[i] = 0.0f;
        ull bp[4];
        #pragma unroll
        for (int ci = 0; ci < 4; ci++) bp[ci] = *(const ull*)&sB3[cb * 8 + 2 * ci];

        #pragma unroll
        for (int pass = 0; pass < 4; pass++) {       // v in chunks of 4
            ull acc2[4][4];
            #pragma unroll
            for (int ci = 0; ci < 4; ci++)
                #pragma unroll
                for (int vi = 0; vi < 4; vi++) acc2[ci][vi] = bp[ci];

            #pragma unroll 8
            for (int k = 0; k < 32; k++) {
                ull hs[4];
                #pragma unroll
                for (int vi = 0; vi < 4; vi++)
                    hs[vi] = splat2(sH2[k * 512 + (pass * 4 + vi) * 32 + w]);
                ull wv[4];
                #pragma unroll
                for (int ci = 0; ci < 4; ci++)
                    wv[ci] = *(const ull*)&sW3t[k * 64 + cb * 8 + 2 * ci];
                #pragma unroll
                for (int ci = 0; ci < 4; ci++)
                    #pragma unroll
                    for (int vi = 0; vi < 4; vi++)
                        acc2[ci][vi] = fma2(hs[vi], wv[ci], acc2[ci][vi]);
            }

            #pragma unroll
            for (int vi = 0; vi < 4; vi++) {
                const int v = pass * 4 + vi;
                float m = sA[7 * 512 + v * 32 + w];
                #pragma unroll
                for (int ci = 0; ci < 4; ci++) {
                    float lo, hi; unpack2(acc2[ci][vi], lo, hi);
                    float a0 = fmaxf(lo, 0.0f) * m;
                    float a1 = fmaxf(hi, 0.0f) * m;
                    int c0 = cb * 8 + 2 * ci;
                    Am[((n * CO + c0)     * VV + (v0 + v)) * VV + w0 + w] = a0;
                    Am[((n * CO + c0 + 1) * VV + (v0 + v)) * VV + w0 + w] = a1;
                    cs[2 * ci]     += a0;
                    cs[2 * ci + 1] += a1;
                }
            }
        }
        #pragma unroll
        for (int i = 0; i < 8; i++)
            atomicAdd(&g_colsum[(n * CO + cb * 8 + i) * VV + w0 + w], cs[i]);
    }
}

// ---------------------------------------------------------------------------
// K3: per (n,c): out[t,w] = Dl[w] * sum_v x'[t,v] * Am[v,w]
// Double-buffered Am streaming, normalized An written in the prefetch path,
// f32x2 packed inner loop. Block = (n, c, 128-wide w tile).
// ---------------------------------------------------------------------------
#define S3_X   0                  // 24576 floats
#define S3_AM  24576              // 2 x 32x128 = 8192 (double buffer)
#define S3_DL  32768              // 128
#define S3_FLOATS 32896
#define S3_BYTES  (S3_FLOATS * 4)

__global__ __launch_bounds__(256) void out_kernel(float* __restrict__ out,
                                                  float* __restrict__ An)
{
    extern __shared__ float s[];
    float* sX  = s + S3_X;
    float* sAm = s + S3_AM;
    float* sDl = s + S3_DL;

    const int tid = threadIdx.x;
    const int w0  = blockIdx.x * 128;
    const int c   = blockIdx.y;
    const int n   = blockIdx.z;
    const int nc  = n * CO + c;

    // x'[64][384] -> smem
    const float4* xb4 = (const float4*)(g_xp + nc * PP);
    float4* sX4 = (float4*)sX;
    #pragma unroll
    for (int r = 0; r < 24; r++) sX4[tid + r * 256] = xb4[tid + r * 256];

    if (tid < 128) {
        float csv = g_colsum[nc * VV + w0 + tid];
        sDl[tid] = 1.0f / (csv + EPS_);
    }
    __syncthreads();

    const int c4   = tid & 31;          // float4 column for streaming
    const int rrow = tid >> 5;          // streaming row base
    const float4 dl4 = ((const float4*)sDl)[c4];

    float* Anb = An + nc * VV * VV + w0;

    // chunk 0: load -> smem buf0 + normalized An write
    {
        float4 cur[4];
        #pragma unroll
        for (int r = 0; r < 4; r++)
            cur[r] = *((const float4*)(Anb + (rrow + 8 * r) * VV) + c4);
        #pragma unroll
        for (int r = 0; r < 4; r++) {
            ((float4*)sAm)[(rrow + 8 * r) * 32 + c4] = cur[r];
            float4 o4;
            o4.x = cur[r].x * dl4.x; o4.y = cur[r].y * dl4.y;
            o4.z = cur[r].z * dl4.z; o4.w = cur[r].w * dl4.w;
            *((float4*)(Anb + (rrow + 8 * r) * VV) + c4) = o4;
        }
    }
    __syncthreads();

    const int tx = tid & 31;   // w pairs: 2*tx + 64*j
    const int ty = tid >> 5;   // t: ty + 8*i
    ull acc2[8][2];
    #pragma unroll
    for (int i = 0; i < 8; i++) {
        acc2[i][0] = pack2(0.0f, 0.0f);
        acc2[i][1] = pack2(0.0f, 0.0f);
    }

    for (int kc = 0; kc < 12; kc++) {
        // prefetch chunk kc+1 while computing chunk kc
        float4 nxt[4];
        if (kc < 11) {
            const int vb = (kc + 1) * 32;
            #pragma unroll
            for (int r = 0; r < 4; r++)
                nxt[r] = *((const float4*)(Anb + (vb + rrow + 8 * r) * VV) + c4);
        }

        const float* bufc = sAm + (kc & 1) * 4096;
        #pragma unroll
        for (int v4 = 0; v4 < 8; v4++) {
            float4 xq[8];
            #pragma unroll
            for (int i = 0; i < 8; i++)
                xq[i] = *(const float4*)&sX[(ty + 8 * i) * VV + kc * 32 + v4 * 4];
            #pragma unroll
            for (int vv = 0; vv < 4; vv++) {
                ull av0 = *(const ull*)&bufc[(v4 * 4 + vv) * 128 + 2 * tx];
                ull av1 = *(const ull*)&bufc[(v4 * 4 + vv) * 128 + 2 * tx + 64];
                #pragma unroll
                for (int i = 0; i < 8; i++) {
                    float xs = (vv == 0) ? xq[i].x : (vv == 1) ? xq[i].y
                             : (vv == 2) ? xq[i].z : xq[i].w;
                    ull sv = splat2(xs);
                    acc2[i][0] = fma2(sv, av0, acc2[i][0]);
                    acc2[i][1] = fma2(sv, av1, acc2[i][1]);
                }
            }
        }
        __syncthreads();   // all readers done with bufc

        if (kc < 11) {
            float* bufn = sAm + ((kc + 1) & 1) * 4096;
            const int vb = (kc + 1) * 32;
            #pragma unroll
            for (int r = 0; r < 4; r++) {
                ((float4*)bufn)[(rrow + 8 * r) * 32 + c4] = nxt[r];
                float4 o4;
                o4.x = nxt[r].x * dl4.x; o4.y = nxt[r].y * dl4.y;
                o4.z = nxt[r].z * dl4.z; o4.w = nxt[r].w * dl4.w;
                *((float4*)(Anb + (vb + rrow + 8 * r) * VV) + c4) = o4;
            }
            __syncthreads();  // bufn filled before next compute
        }
    }

    // epilogue: scale by Dl and store out as float2 pairs
    float2 dlp[2];
    #pragma unroll
    for (int j = 0; j < 2; j++) dlp[j] = *(const float2*)&sDl[2 * tx + 64 * j];
    float* ob = out + nc * PP + w0;
    #pragma unroll
    for (int i = 0; i < 8; i++) {
        const int t = ty + 8 * i;
        #pragma unroll
        for (int j = 0; j < 2; j++) {
            float lo, hi; unpack2(acc2[i][j], lo, hi);
            float2 o; o.x = lo * dlp[j].x; o.y = hi * dlp[j].y;
            *(float2*)&ob[t * VV + 2 * tx + 64 * j] = o;
        }
    }
}

// ---------------------------------------------------------------------------
extern "C" void kernel_launch(void* const* d_in, const int* in_sizes, int n_in,
                              void* d_out, int out_size) {
    const float* x      = (const float*)d_in[0];
    const float* A      = (const float*)d_in[1];
    const float* conv_w = (const float*)d_in[2];
    const float* conv_b = (const float*)d_in[3];
    const float* w1     = (const float*)d_in[4];
    const float* b1     = (const float*)d_in[5];
    const float* w2     = (const float*)d_in[6];
    const float* b2     = (const float*)d_in[7];
    const float* w3     = (const float*)d_in[8];
    const float* b3     = (const float*)d_in[9];

    float* out = (float*)d_out;
    float* An  = out + XP_ELEMS;   // tuple layout: out first, then An

    cudaFuncSetAttribute(mlp_kernel, cudaFuncAttributeMaxDynamicSharedMemorySize, S2_BYTES);
    cudaFuncSetAttribute(out_kernel, cudaFuncAttributeMaxDynamicSharedMemorySize, S3_BYTES);

    zero_colsum_kernel<<<(CS_ELEMS + 255) / 256, 256>>>();
    conv_kernel<<<dim3(PP / 64, NB), 256>>>(x, conv_w, conv_b);
    mlp_kernel<<<dim3(VV / 32, VV / 16, NB), 256, S2_BYTES>>>(A, w1, b1, w2, b2, w3, b3, An);
    out_kernel<<<dim3(VV / 128, CO, NB), 256, S3_BYTES>>>(out, An);
}

// round 3
// speedup vs baseline: 1.2644x; 1.0012x over previous
#include <cuda_runtime.h>

#define EPS_ 0.001f

// Problem constants
#define NB   16
#define CIN  64
#define CO   64
#define TT   64
#define VV   384
#define PP   (TT*VV)          // 24576 positions per (n, channel)
#define XP_ELEMS  (NB*CO*PP)  // 25165824
#define CS_ELEMS  (NB*CO*VV)  // 393216

typedef unsigned long long ull;

// Scratch (no cudaMalloc allowed)
__device__ float g_xp[XP_ELEMS];
__device__ float g_colsum[CS_ELEMS];

// ---------------------------------------------------------------------------
// packed f32x2 helpers (Blackwell FFMA2 path — only reachable via PTX)
// ---------------------------------------------------------------------------
__device__ __forceinline__ ull pack2(float lo, float hi) {
    ull r; asm("mov.b64 %0, {%1, %2};" : "=l"(r) : "f"(lo), "f"(hi)); return r;
}
__device__ __forceinline__ ull splat2(float v) {
    ull r; asm("mov.b64 %0, {%1, %1};" : "=l"(r) : "f"(v)); return r;
}
__device__ __forceinline__ void unpack2(ull p, float& lo, float& hi) {
    asm("mov.b64 {%0, %1}, %2;" : "=f"(lo), "=f"(hi) : "l"(p));
}
__device__ __forceinline__ ull fma2(ull a, ull b, ull c) {
    ull d; asm("fma.rn.f32x2 %0, %1, %2, %3;" : "=l"(d) : "l"(a), "l"(b), "l"(c)); return d;
}

// ---------------------------------------------------------------------------
// K0: zero the column-sum accumulator
// ---------------------------------------------------------------------------
__global__ void zero_colsum_kernel() {
    int i = blockIdx.x * blockDim.x + threadIdx.x;
    if (i < CS_ELEMS) g_colsum[i] = 0.0f;
}

// ---------------------------------------------------------------------------
// K1: x'[n,o,p] = sum_c conv_w[o,c] * x[n,c,p] + conv_b[o]
// ---------------------------------------------------------------------------
__global__ __launch_bounds__(256) void conv_kernel(const float* __restrict__ x,
                                                   const float* __restrict__ w,
                                                   const float* __restrict__ b) {
    __shared__ float sW[64 * 65];
    __shared__ float sX[64 * 64];
    const int n   = blockIdx.y;
    const int p0  = blockIdx.x * 64;
    const int tid = threadIdx.x;

    for (int i = tid; i < 4096; i += 256)
        sW[(i >> 6) * 65 + (i & 63)] = w[i];

    const float* xb = x + n * CIN * PP;
    #pragma unroll
    for (int r = 0; r < 16; r++) {
        int idx = tid + 256 * r;
        int c = idx >> 6, p = idx & 63;
        sX[c * 64 + p] = xb[c * PP + p0 + p];
    }
    __syncthreads();

    const int ob = tid >> 4;
    const int px = tid & 15;
    float acc[4][4];
    #pragma unroll
    for (int i = 0; i < 4; i++)
        #pragma unroll
        for (int j = 0; j < 4; j++) acc[i][j] = 0.0f;

    #pragma unroll 8
    for (int c = 0; c < 64; c++) {
        float xv[4], wv[4];
        #pragma unroll
        for (int j = 0; j < 4; j++) xv[j] = sX[c * 64 + px + 16 * j];
        #pragma unroll
        for (int i = 0; i < 4; i++) wv[i] = sW[(ob + 16 * i) * 65 + c];
        #pragma unroll
        for (int i = 0; i < 4; i++)
            #pragma unroll
            for (int j = 0; j < 4; j++) acc[i][j] += wv[i] * xv[j];
    }

    #pragma unroll
    for (int i = 0; i < 4; i++) {
        int o = ob + 16 * i;
        float bo = __ldg(&b[o]);
        float* op = g_xp + (n * CO + o) * PP + p0;
        #pragma unroll
        for (int j = 0; j < 4; j++) op[px + 16 * j] = acc[i][j] + bo;
    }
}

// ---------------------------------------------------------------------------
// K2: MLP 7->16->32->64 (ReLU each stage), mask multiply -> Am + colsum.
// Fused stage1+2 in registers (no sH1), f32x2 packed math, 2 blocks/SM.
// Block = one n, tile of 16 v x 32 w = 512 positions.
// ---------------------------------------------------------------------------
#define S2_A    0                 // sA  [8][512]          4096
#define S2_H2   4096              // sH2 [32][512]         16384
#define S2_W1T  20480             // w1t [7][16] (pad 128) 128
#define S2_B1   20608             // 16
#define S2_W2T  20624             // w2t [16][32]          512
#define S2_B2   21136             // 32
#define S2_W3T  21168             // w3t [32][64]          2048
#define S2_B3   23216             // 64
#define S2_FLOATS 23280
#define S2_BYTES  (S2_FLOATS * 4)

__global__ __launch_bounds__(256, 2) void mlp_kernel(
    const float* __restrict__ A,
    const float* __restrict__ w1, const float* __restrict__ b1,
    const float* __restrict__ w2, const float* __restrict__ b2,
    const float* __restrict__ w3, const float* __restrict__ b3,
    float* __restrict__ Am)
{
    extern __shared__ float s[];
    float* sA   = s + S2_A;
    float* sH2  = s + S2_H2;
    float* sW1t = s + S2_W1T; float* sB1 = s + S2_B1;
    float* sW2t = s + S2_W2T; float* sB2 = s + S2_B2;
    float* sW3t = s + S2_W3T; float* sB3 = s + S2_B3;

    const int tid = threadIdx.x;
    const int w0  = blockIdx.x * 32;
    const int v0  = blockIdx.y * 16;
    const int n   = blockIdx.z;

    // weights -> smem (transposed so channel pairs are contiguous)
    if (tid < 112) { int c = tid / 7, k = tid % 7; sW1t[k * 16 + c] = w1[tid]; }
    if (tid < 16)  sB1[tid] = b1[tid];
    for (int i = tid; i < 512; i += 256)  { int c = i >> 4, k = i & 15; sW2t[k * 32 + c] = w2[i]; }
    if (tid < 32)  sB2[tid] = b2[tid];
    for (int i = tid; i < 2048; i += 256) { int c = i >> 5, k = i & 31; sW3t[k * 64 + c] = w3[i]; }
    if (tid < 64)  sB3[tid] = b3[tid];

    // A tile: 8 channels x 16 v x 32 w (channel 7 = mask)
    {
        const int w   = tid & 31;
        const int sub = tid >> 5;
        const float* Ab = A + n * 8 * VV * VV;
        #pragma unroll
        for (int k = 0; k < 8; k++)
            #pragma unroll
            for (int vi = 0; vi < 2; vi++) {
                int v = sub + vi * 8;
                sA[k * 512 + v * 32 + w] = Ab[(k * VV + v0 + v) * VV + w0 + w];
            }
    }
    __syncthreads();

    // ---- fused stage 1+2: per position, H1 and H2 in registers ----
    #pragma unroll
    for (int jj = 0; jj < 2; jj++) {
        const int p = tid + jj * 256;
        float av[7];
        #pragma unroll
        for (int k = 0; k < 7; k++) av[k] = sA[k * 512 + p];

        ull h1p[8];
        #pragma unroll
        for (int ci = 0; ci < 8; ci++) h1p[ci] = *(const ull*)&sB1[2 * ci];
        #pragma unroll
        for (int k = 0; k < 7; k++) {
            ull sv = splat2(av[k]);
            #pragma unroll
            for (int ci = 0; ci < 8; ci++)
                h1p[ci] = fma2(sv, *(const ull*)&sW1t[k * 16 + 2 * ci], h1p[ci]);
        }
        float h1[16];
        #pragma unroll
        for (int ci = 0; ci < 8; ci++) {
            float lo, hi; unpack2(h1p[ci], lo, hi);
            h1[2 * ci]     = fmaxf(lo, 0.0f);
            h1[2 * ci + 1] = fmaxf(hi, 0.0f);
        }

        ull h2p[16];
        #pragma unroll
        for (int ci = 0; ci < 16; ci++) h2p[ci] = *(const ull*)&sB2[2 * ci];
        #pragma unroll
        for (int k = 0; k < 16; k++) {
            ull sv = splat2(h1[k]);
            #pragma unroll
            for (int ci = 0; ci < 16; ci++)
                h2p[ci] = fma2(sv, *(const ull*)&sW2t[k * 32 + 2 * ci], h2p[ci]);
        }
        #pragma unroll
        for (int ci = 0; ci < 16; ci++) {
            float lo, hi; unpack2(h2p[ci], lo, hi);
            sH2[(2 * ci) * 512 + p]     = fmaxf(lo, 0.0f);
            sH2[(2 * ci + 1) * 512 + p] = fmaxf(hi, 0.0f);
        }
    }
    __syncthreads();

    // ---- stage 3: 32 -> 64, relu, mask, Am write + colsum ----
    {
        const int w  = tid & 31;
        const int cb = tid >> 5;       // 8 groups of 8 channels (4 pairs)
        float cs[8];
        #pragma unroll
        for (int i = 0; i < 8; i++) cs[i] = 0.0f;
        ull bp[4];
        #pragma unroll
        for (int ci = 0; ci < 4; ci++) bp[ci] = *(const ull*)&sB3[cb * 8 + 2 * ci];

        #pragma unroll
        for (int pass = 0; pass < 4; pass++) {       // v in chunks of 4
            ull acc2[4][4];
            #pragma unroll
            for (int ci = 0; ci < 4; ci++)
                #pragma unroll
                for (int vi = 0; vi < 4; vi++) acc2[ci][vi] = bp[ci];

            #pragma unroll 8
            for (int k = 0; k < 32; k++) {
                ull hs[4];
                #pragma unroll
                for (int vi = 0; vi < 4; vi++)
                    hs[vi] = splat2(sH2[k * 512 + (pass * 4 + vi) * 32 + w]);
                ull wv[4];
                #pragma unroll
                for (int ci = 0; ci < 4; ci++)
                    wv[ci] = *(const ull*)&sW3t[k * 64 + cb * 8 + 2 * ci];
                #pragma unroll
                for (int ci = 0; ci < 4; ci++)
                    #pragma unroll
                    for (int vi = 0; vi < 4; vi++)
                        acc2[ci][vi] = fma2(hs[vi], wv[ci], acc2[ci][vi]);
            }

            #pragma unroll
            for (int vi = 0; vi < 4; vi++) {
                const int v = pass * 4 + vi;
                float m = sA[7 * 512 + v * 32 + w];
                #pragma unroll
                for (int ci = 0; ci < 4; ci++) {
                    float lo, hi; unpack2(acc2[ci][vi], lo, hi);
                    float a0 = fmaxf(lo, 0.0f) * m;
                    float a1 = fmaxf(hi, 0.0f) * m;
                    int c0 = cb * 8 + 2 * ci;
                    Am[((n * CO + c0)     * VV + (v0 + v)) * VV + w0 + w] = a0;
                    Am[((n * CO + c0 + 1) * VV + (v0 + v)) * VV + w0 + w] = a1;
                    cs[2 * ci]     += a0;
                    cs[2 * ci + 1] += a1;
                }
            }
        }
        #pragma unroll
        for (int i = 0; i < 8; i++)
            atomicAdd(&g_colsum[(n * CO + cb * 8 + i) * VV + w0 + w], cs[i]);
    }
}

// ---------------------------------------------------------------------------
// K3: per (n,c): out[t,w] = Dl[w] * sum_v x'[t,v] * Am[v,w]
// 512 threads (16 warps/SM), double-buffered Am streaming, normalized An
// written in the prefetch path, f32x2 inner loop. Block = (n, c, 128-w tile).
// ---------------------------------------------------------------------------
#define S3_X   0                  // 24576 floats
#define S3_AM  24576              // 2 x 32x128 = 8192 (double buffer)
#define S3_DL  32768              // 128
#define S3_FLOATS 32896
#define S3_BYTES  (S3_FLOATS * 4)

__global__ __launch_bounds__(512) void out_kernel(float* __restrict__ out,
                                                  float* __restrict__ An)
{
    extern __shared__ float s[];
    float* sX  = s + S3_X;
    float* sAm = s + S3_AM;
    float* sDl = s + S3_DL;

    const int tid = threadIdx.x;
    const int w0  = blockIdx.x * 128;
    const int c   = blockIdx.y;
    const int n   = blockIdx.z;
    const int nc  = n * CO + c;

    // x'[64][384] -> smem
    const float4* xb4 = (const float4*)(g_xp + nc * PP);
    float4* sX4 = (float4*)sX;
    #pragma unroll
    for (int r = 0; r < 12; r++) sX4[tid + r * 512] = xb4[tid + r * 512];

    if (tid < 128) {
        float csv = g_colsum[nc * VV + w0 + tid];
        sDl[tid] = 1.0f / (csv + EPS_);
    }
    __syncthreads();

    const int c4   = tid & 31;          // float4 column for streaming
    const int rrow = tid >> 5;          // 0..15, rows rrow and rrow+16
    const float4 dl4 = ((const float4*)sDl)[c4];

    float* Anb = An + nc * VV * VV + w0;

    // chunk 0: load -> smem buf0 + normalized An write
    {
        float4 cur[2];
        #pragma unroll
        for (int r = 0; r < 2; r++)
            cur[r] = *((const float4*)(Anb + (rrow + 16 * r) * VV) + c4);
        #pragma unroll
        for (int r = 0; r < 2; r++) {
            ((float4*)sAm)[(rrow + 16 * r) * 32 + c4] = cur[r];
            float4 o4;
            o4.x = cur[r].x * dl4.x; o4.y = cur[r].y * dl4.y;
            o4.z = cur[r].z * dl4.z; o4.w = cur[r].w * dl4.w;
            *((float4*)(Anb + (rrow + 16 * r) * VV) + c4) = o4;
        }
    }
    __syncthreads();

    const int tx = tid & 31;   // w pairs: 2*tx + 64*j
    const int ty = tid >> 5;   // 0..15, t = ty + 16*i
    ull acc2[4][2];
    #pragma unroll
    for (int i = 0; i < 4; i++) {
        acc2[i][0] = pack2(0.0f, 0.0f);
        acc2[i][1] = pack2(0.0f, 0.0f);
    }

    for (int kc = 0; kc < 12; kc++) {
        // prefetch chunk kc+1 while computing chunk kc
        float4 nxt[2];
        if (kc < 11) {
            const int vb = (kc + 1) * 32;
            #pragma unroll
            for (int r = 0; r < 2; r++)
                nxt[r] = *((const float4*)(Anb + (vb + rrow + 16 * r) * VV) + c4);
        }

        const float* bufc = sAm + (kc & 1) * 4096;
        #pragma unroll
        for (int v4 = 0; v4 < 8; v4++) {
            float4 xq[4];
            #pragma unroll
            for (int i = 0; i < 4; i++)
                xq[i] = *(const float4*)&sX[(ty + 16 * i) * VV + kc * 32 + v4 * 4];
            #pragma unroll
            for (int vv = 0; vv < 4; vv++) {
                ull av0 = *(const ull*)&bufc[(v4 * 4 + vv) * 128 + 2 * tx];
                ull av1 = *(const ull*)&bufc[(v4 * 4 + vv) * 128 + 2 * tx + 64];
                #pragma unroll
                for (int i = 0; i < 4; i++) {
                    float xs = (vv == 0) ? xq[i].x : (vv == 1) ? xq[i].y
                             : (vv == 2) ? xq[i].z : xq[i].w;
                    ull sv = splat2(xs);
                    acc2[i][0] = fma2(sv, av0, acc2[i][0]);
                    acc2[i][1] = fma2(sv, av1, acc2[i][1]);
                }
            }
        }
        __syncthreads();   // all readers done with bufc

        if (kc < 11) {
            float* bufn = sAm + ((kc + 1) & 1) * 4096;
            const int vb = (kc + 1) * 32;
            #pragma unroll
            for (int r = 0; r < 2; r++) {
                ((float4*)bufn)[(rrow + 16 * r) * 32 + c4] = nxt[r];
                float4 o4;
                o4.x = nxt[r].x * dl4.x; o4.y = nxt[r].y * dl4.y;
                o4.z = nxt[r].z * dl4.z; o4.w = nxt[r].w * dl4.w;
                *((float4*)(Anb + (vb + rrow + 16 * r) * VV) + c4) = o4;
            }
            __syncthreads();  // bufn filled before next compute
        }
    }

    // epilogue: scale by Dl and store out as float2 pairs
    float2 dlp[2];
    #pragma unroll
    for (int j = 0; j < 2; j++) dlp[j] = *(const float2*)&sDl[2 * tx + 64 * j];
    float* ob = out + nc * PP + w0;
    #pragma unroll
    for (int i = 0; i < 4; i++) {
        const int t = ty + 16 * i;
        #pragma unroll
        for (int j = 0; j < 2; j++) {
            float lo, hi; unpack2(acc2[i][j], lo, hi);
            float2 o; o.x = lo * dlp[j].x; o.y = hi * dlp[j].y;
            *(float2*)&ob[t * VV + 2 * tx + 64 * j] = o;
        }
    }
}

// ---------------------------------------------------------------------------
extern "C" void kernel_launch(void* const* d_in, const int* in_sizes, int n_in,
                              void* d_out, int out_size) {
    const float* x      = (const float*)d_in[0];
    const float* A      = (const float*)d_in[1];
    const float* conv_w = (const float*)d_in[2];
    const float* conv_b = (const float*)d_in[3];
    const float* w1     = (const float*)d_in[4];
    const float* b1     = (const float*)d_in[5];
    const float* w2     = (const float*)d_in[6];
    const float* b2     = (const float*)d_in[7];
    const float* w3     = (const float*)d_in[8];
    const float* b3     = (const float*)d_in[9];

    float* out = (float*)d_out;
    float* An  = out + XP_ELEMS;   // tuple layout: out first, then An

    cudaFuncSetAttribute(mlp_kernel, cudaFuncAttributeMaxDynamicSharedMemorySize, S2_BYTES);
    cudaFuncSetAttribute(out_kernel, cudaFuncAttributeMaxDynamicSharedMemorySize, S3_BYTES);

    zero_colsum_kernel<<<(CS_ELEMS + 255) / 256, 256>>>();
    conv_kernel<<<dim3(PP / 64, NB), 256>>>(x, conv_w, conv_b);
    mlp_kernel<<<dim3(VV / 32, VV / 16, NB), 256, S2_BYTES>>>(A, w1, b1, w2, b2, w3, b3, An);
    out_kernel<<<dim3(VV / 128, CO, NB), 512, S3_BYTES>>>(out, An);
}

// round 4
// speedup vs baseline: 1.5252x; 1.2062x over previous
#include <cuda_runtime.h>
#include <cstdint>

#define EPS_ 0.001f

// Problem constants
#define NB   16
#define CIN  64
#define CO   64
#define TT   64
#define VV   384
#define PP   (TT*VV)          // 24576 positions per (n, channel)
#define XP_ELEMS  (NB*CO*PP)  // 25165824
#define CS_ELEMS  (NB*CO*VV)  // 393216

typedef unsigned long long ull;

// Scratch (no cudaMalloc allowed)
__device__ float g_xp[XP_ELEMS];
__device__ float g_colsum[CS_ELEMS];

// ---------------------------------------------------------------------------
// packed f32x2 helpers
// ---------------------------------------------------------------------------
__device__ __forceinline__ ull pack2(float lo, float hi) {
    ull r; asm("mov.b64 %0, {%1, %2};" : "=l"(r) : "f"(lo), "f"(hi)); return r;
}
__device__ __forceinline__ ull splat2(float v) {
    ull r; asm("mov.b64 %0, {%1, %1};" : "=l"(r) : "f"(v)); return r;
}
__device__ __forceinline__ void unpack2(ull p, float& lo, float& hi) {
    asm("mov.b64 {%0, %1}, %2;" : "=f"(lo), "=f"(hi) : "l"(p));
}
__device__ __forceinline__ ull fma2(ull a, ull b, ull c) {
    ull d; asm("fma.rn.f32x2 %0, %1, %2, %3;" : "=l"(d) : "l"(a), "l"(b), "l"(c)); return d;
}

// ---------------------------------------------------------------------------
// mbarrier helpers
// ---------------------------------------------------------------------------
__device__ __forceinline__ uint32_t smem_u32(const void* p) {
    uint32_t a;
    asm("{ .reg .u64 t; cvta.to.shared.u64 t, %1; cvt.u32.u64 %0, t; }" : "=r"(a) : "l"(p));
    return a;
}
__device__ __forceinline__ void mbar_init(uint32_t a, uint32_t cnt) {
    asm volatile("mbarrier.init.shared.b64 [%0], %1;" :: "r"(a), "r"(cnt) : "memory");
}
__device__ __forceinline__ void mbar_arrive(uint32_t a) {
    asm volatile("mbarrier.arrive.shared.b64 _, [%0];" :: "r"(a) : "memory");
}
__device__ __forceinline__ void mbar_wait(uint32_t a, uint32_t parity) {
    uint32_t done;
    asm volatile(
        "{\n\t.reg .pred p;\n\t"
        "mbarrier.try_wait.parity.shared.b64 p, [%1], %2;\n\t"
        "selp.b32 %0, 1, 0, p;\n\t}"
        : "=r"(done) : "r"(a), "r"(parity) : "memory");
    if (!done) {
        asm volatile(
            "{\n\t.reg .pred P1;\n\t"
            "WL_%=:\n\t"
            "mbarrier.try_wait.parity.shared.b64 P1, [%0], %1;\n\t"
            "@P1 bra.uni WD_%=;\n\t"
            "bra.uni WL_%=;\n\t"
            "WD_%=:\n\t}"
            :: "r"(a), "r"(parity) : "memory");
    }
}

// ---------------------------------------------------------------------------
// K0: zero the column-sum accumulator
// ---------------------------------------------------------------------------
__global__ void zero_colsum_kernel() {
    int i = blockIdx.x * blockDim.x + threadIdx.x;
    if (i < CS_ELEMS) g_colsum[i] = 0.0f;
}

// ---------------------------------------------------------------------------
// K1: x'[n,o,p] = sum_c conv_w[o,c] * x[n,c,p] + conv_b[o]
// ---------------------------------------------------------------------------
__global__ __launch_bounds__(256) void conv_kernel(const float* __restrict__ x,
                                                   const float* __restrict__ w,
                                                   const float* __restrict__ b) {
    __shared__ float sW[64 * 65];
    __shared__ float sX[64 * 64];
    const int n   = blockIdx.y;
    const int p0  = blockIdx.x * 64;
    const int tid = threadIdx.x;

    for (int i = tid; i < 4096; i += 256)
        sW[(i >> 6) * 65 + (i & 63)] = w[i];

    const float* xb = x + n * CIN * PP;
    #pragma unroll
    for (int r = 0; r < 16; r++) {
        int idx = tid + 256 * r;
        int c = idx >> 6, p = idx & 63;
        sX[c * 64 + p] = xb[c * PP + p0 + p];
    }
    __syncthreads();

    const int ob = tid >> 4;
    const int px = tid & 15;
    float acc[4][4];
    #pragma unroll
    for (int i = 0; i < 4; i++)
        #pragma unroll
        for (int j = 0; j < 4; j++) acc[i][j] = 0.0f;

    #pragma unroll 8
    for (int c = 0; c < 64; c++) {
        float xv[4], wv[4];
        #pragma unroll
        for (int j = 0; j < 4; j++) xv[j] = sX[c * 64 + px + 16 * j];
        #pragma unroll
        for (int i = 0; i < 4; i++) wv[i] = sW[(ob + 16 * i) * 65 + c];
        #pragma unroll
        for (int i = 0; i < 4; i++)
            #pragma unroll
            for (int j = 0; j < 4; j++) acc[i][j] += wv[i] * xv[j];
    }

    #pragma unroll
    for (int i = 0; i < 4; i++) {
        int o = ob + 16 * i;
        float bo = __ldg(&b[o]);
        float* op = g_xp + (n * CO + o) * PP + p0;
        #pragma unroll
        for (int j = 0; j < 4; j++) op[px + 16 * j] = acc[i][j] + bo;
    }
}

// ---------------------------------------------------------------------------
// K2: MLP 7->16->32->64 (ReLU each stage), mask multiply -> Am + colsum.
// (unchanged from R3)
// ---------------------------------------------------------------------------
#define S2_A    0
#define S2_H2   4096
#define S2_W1T  20480
#define S2_B1   20608
#define S2_W2T  20624
#define S2_B2   21136
#define S2_W3T  21168
#define S2_B3   23216
#define S2_FLOATS 23280
#define S2_BYTES  (S2_FLOATS * 4)

__global__ __launch_bounds__(256, 2) void mlp_kernel(
    const float* __restrict__ A,
    const float* __restrict__ w1, const float* __restrict__ b1,
    const float* __restrict__ w2, const float* __restrict__ b2,
    const float* __restrict__ w3, const float* __restrict__ b3,
    float* __restrict__ Am)
{
    extern __shared__ float s[];
    float* sA   = s + S2_A;
    float* sH2  = s + S2_H2;
    float* sW1t = s + S2_W1T; float* sB1 = s + S2_B1;
    float* sW2t = s + S2_W2T; float* sB2 = s + S2_B2;
    float* sW3t = s + S2_W3T; float* sB3 = s + S2_B3;

    const int tid = threadIdx.x;
    const int w0  = blockIdx.x * 32;
    const int v0  = blockIdx.y * 16;
    const int n   = blockIdx.z;

    if (tid < 112) { int c = tid / 7, k = tid % 7; sW1t[k * 16 + c] = w1[tid]; }
    if (tid < 16)  sB1[tid] = b1[tid];
    for (int i = tid; i < 512; i += 256)  { int c = i >> 4, k = i & 15; sW2t[k * 32 + c] = w2[i]; }
    if (tid < 32)  sB2[tid] = b2[tid];
    for (int i = tid; i < 2048; i += 256) { int c = i >> 5, k = i & 31; sW3t[k * 64 + c] = w3[i]; }
    if (tid < 64)  sB3[tid] = b3[tid];

    {
        const int w   = tid & 31;
        const int sub = tid >> 5;
        const float* Ab = A + n * 8 * VV * VV;
        #pragma unroll
        for (int k = 0; k < 8; k++)
            #pragma unroll
            for (int vi = 0; vi < 2; vi++) {
                int v = sub + vi * 8;
                sA[k * 512 + v * 32 + w] = Ab[(k * VV + v0 + v) * VV + w0 + w];
            }
    }
    __syncthreads();

    #pragma unroll
    for (int jj = 0; jj < 2; jj++) {
        const int p = tid + jj * 256;
        float av[7];
        #pragma unroll
        for (int k = 0; k < 7; k++) av[k] = sA[k * 512 + p];

        ull h1p[8];
        #pragma unroll
        for (int ci = 0; ci < 8; ci++) h1p[ci] = *(const ull*)&sB1[2 * ci];
        #pragma unroll
        for (int k = 0; k < 7; k++) {
            ull sv = splat2(av[k]);
            #pragma unroll
            for (int ci = 0; ci < 8; ci++)
                h1p[ci] = fma2(sv, *(const ull*)&sW1t[k * 16 + 2 * ci], h1p[ci]);
        }
        float h1[16];
        #pragma unroll
        for (int ci = 0; ci < 8; ci++) {
            float lo, hi; unpack2(h1p[ci], lo, hi);
            h1[2 * ci]     = fmaxf(lo, 0.0f);
            h1[2 * ci + 1] = fmaxf(hi, 0.0f);
        }

        ull h2p[16];
        #pragma unroll
        for (int ci = 0; ci < 16; ci++) h2p[ci] = *(const ull*)&sB2[2 * ci];
        #pragma unroll
        for (int k = 0; k < 16; k++) {
            ull sv = splat2(h1[k]);
            #pragma unroll
            for (int ci = 0; ci < 16; ci++)
                h2p[ci] = fma2(sv, *(const ull*)&sW2t[k * 32 + 2 * ci], h2p[ci]);
        }
        #pragma unroll
        for (int ci = 0; ci < 16; ci++) {
            float lo, hi; unpack2(h2p[ci], lo, hi);
            sH2[(2 * ci) * 512 + p]     = fmaxf(lo, 0.0f);
            sH2[(2 * ci + 1) * 512 + p] = fmaxf(hi, 0.0f);
        }
    }
    __syncthreads();

    {
        const int w  = tid & 31;
        const int cb = tid >> 5;
        float cs[8];
        #pragma unroll
        for (int i = 0; i < 8; i++) cs[i] = 0.0f;
        ull bp[4];
        #pragma unroll
        for (int ci = 0; ci < 4; ci++) bp[ci] = *(const ull*)&sB3[cb * 8 + 2 * ci];

        #pragma unroll
        for (int pass = 0; pass < 4; pass++) {
            ull acc2[4][4];
            #pragma unroll
            for (int ci = 0; ci < 4; ci++)
                #pragma unroll
                for (int vi = 0; vi < 4; vi++) acc2[ci][vi] = bp[ci];

            #pragma unroll 8
            for (int k = 0; k < 32; k++) {
                ull hs[4];
                #pragma unroll
                for (int vi = 0; vi < 4; vi++)
                    hs[vi] = splat2(sH2[k * 512 + (pass * 4 + vi) * 32 + w]);
                ull wv[4];
                #pragma unroll
                for (int ci = 0; ci < 4; ci++)
                    wv[ci] = *(const ull*)&sW3t[k * 64 + cb * 8 + 2 * ci];
                #pragma unroll
                for (int ci = 0; ci < 4; ci++)
                    #pragma unroll
                    for (int vi = 0; vi < 4; vi++)
                        acc2[ci][vi] = fma2(hs[vi], wv[ci], acc2[ci][vi]);
            }

            #pragma unroll
            for (int vi = 0; vi < 4; vi++) {
                const int v = pass * 4 + vi;
                float m = sA[7 * 512 + v * 32 + w];
                #pragma unroll
                for (int ci = 0; ci < 4; ci++) {
                    float lo, hi; unpack2(acc2[ci][vi], lo, hi);
                    float a0 = fmaxf(lo, 0.0f) * m;
                    float a1 = fmaxf(hi, 0.0f) * m;
                    int c0 = cb * 8 + 2 * ci;
                    Am[((n * CO + c0)     * VV + (v0 + v)) * VV + w0 + w] = a0;
                    Am[((n * CO + c0 + 1) * VV + (v0 + v)) * VV + w0 + w] = a1;
                    cs[2 * ci]     += a0;
                    cs[2 * ci + 1] += a1;
                }
            }
        }
        #pragma unroll
        for (int i = 0; i < 8; i++)
            atomicAdd(&g_colsum[(n * CO + cb * 8 + i) * VV + w0 + w], cs[i]);
    }
}

// ---------------------------------------------------------------------------
// K3: warp-specialized. Block = (n, c, 192-wide w tile), 384 threads:
//   warps 0..7  consumers: GEMM out[t,w] = Dl[w] * sum_v x'[t,v]*Am[v,w]
//   warps 8..11 producers: stream Am chunks (32 v x 192 w) into a 3-stage
//                          smem ring, write normalized An in the same pass.
// No __syncthreads in the main loop; mbarrier full/empty ring handshake.
// ---------------------------------------------------------------------------
#define BW      192
#define CHUNK_V 32
#define NSTAGE  3
#define STAGE_FLOATS (CHUNK_V * BW)       // 6144
#define S3_DYN_FLOATS (NSTAGE * STAGE_FLOATS + TT * VV)   // 18432 + 24576
#define S3_DYN_BYTES  (S3_DYN_FLOATS * 4)                 // 172032

__global__ __launch_bounds__(384) void out_kernel(float* __restrict__ out,
                                                  float* __restrict__ An)
{
    extern __shared__ float s[];
    float* sAm = s;                               // [3][32][192]
    float* sX  = s + NSTAGE * STAGE_FLOATS;       // [64][384]
    __shared__ float sDl[BW];
    __shared__ __align__(8) ull s_mbar[2 * NSTAGE];   // [full0..2, empty0..2]

    const int tid = threadIdx.x;
    const int w0  = blockIdx.x * BW;
    const int c   = blockIdx.y;
    const int n   = blockIdx.z;
    const int nc  = n * CO + c;

    const uint32_t mb = smem_u32(s_mbar);
    if (tid == 0) {
        #pragma unroll
        for (int st = 0; st < NSTAGE; st++) {
            mbar_init(mb + st * 8, 128);               // full: 128 producer threads
            mbar_init(mb + (NSTAGE + st) * 8, 8);      // empty: 8 consumer warps
        }
    }

    // x'[64][384] -> smem (all threads)
    const float4* xb4 = (const float4*)(g_xp + nc * PP);
    float4* sX4 = (float4*)sX;
    #pragma unroll
    for (int r = 0; r < 16; r++) sX4[tid + r * 384] = xb4[tid + r * 384];

    if (tid < BW) {
        float csv = g_colsum[nc * VV + w0 + tid];
        sDl[tid] = 1.0f / (csv + EPS_);
    }
    __syncthreads();

    float* Anb = An + nc * VV * VV + w0;
    const int wid = tid >> 5;

    if (wid >= 8) {
        // ----------------- PRODUCERS (4 warps, 128 threads) -----------------
        const int ptid = tid - 256;   // 0..127
        int stage = 0, ph = 1;
        for (int kc = 0; kc < 12; kc++) {
            // load chunk kc into registers (12 float4 per thread)
            float4 cur[12];
            int   rowi[12], c4i[12];
            #pragma unroll
            for (int q = 0; q < 12; q++) {
                int idx = ptid + 128 * q;        // 0..1535
                int row = idx / 48;              // v within chunk
                int c4  = idx % 48;              // float4 column
                rowi[q] = row; c4i[q] = c4;
                cur[q] = *((const float4*)(Anb + (kc * CHUNK_V + row) * VV) + c4);
            }
            mbar_wait(mb + (NSTAGE + stage) * 8, ph);
            float* buf = sAm + stage * STAGE_FLOATS;
            #pragma unroll
            for (int q = 0; q < 12; q++) {
                ((float4*)buf)[rowi[q] * 48 + c4i[q]] = cur[q];
                const float4 d4 = ((const float4*)sDl)[c4i[q]];
                float4 o4;
                o4.x = cur[q].x * d4.x; o4.y = cur[q].y * d4.y;
                o4.z = cur[q].z * d4.z; o4.w = cur[q].w * d4.w;
                *((float4*)(Anb + (kc * CHUNK_V + rowi[q]) * VV) + c4i[q]) = o4;
            }
            mbar_arrive(mb + stage * 8);
            if (++stage == NSTAGE) { stage = 0; ph ^= 1; }
        }
    } else {
        // ----------------- CONSUMERS (8 warps, 256 threads) -----------------
        const int tx = tid & 31;      // w pairs: 2*tx + 64*j  (j=0..2)
        const int wc = wid;           // t rows: wc + 8*i     (i=0..7)
        ull acc2[8][3];
        #pragma unroll
        for (int i = 0; i < 8; i++)
            #pragma unroll
            for (int j = 0; j < 3; j++) acc2[i][j] = 0ull;

        int stage = 0, ph = 0;
        for (int kc = 0; kc < 12; kc++) {
            mbar_wait(mb + stage * 8, ph);
            const float* buf = sAm + stage * STAGE_FLOATS;
            #pragma unroll
            for (int v4 = 0; v4 < 8; v4++) {
                float4 xq[8];
                #pragma unroll
                for (int i = 0; i < 8; i++)
                    xq[i] = *(const float4*)&sX[(wc + 8 * i) * VV + kc * CHUNK_V + v4 * 4];
                #pragma unroll
                for (int vv = 0; vv < 4; vv++) {
                    ull av[3];
                    #pragma unroll
                    for (int j = 0; j < 3; j++)
                        av[j] = *(const ull*)&buf[(v4 * 4 + vv) * BW + 2 * tx + 64 * j];
                    #pragma unroll
                    for (int i = 0; i < 8; i++) {
                        float xs = (vv == 0) ? xq[i].x : (vv == 1) ? xq[i].y
                                 : (vv == 2) ? xq[i].z : xq[i].w;
                        ull sv = splat2(xs);
                        #pragma unroll
                        for (int j = 0; j < 3; j++)
                            acc2[i][j] = fma2(sv, av[j], acc2[i][j]);
                    }
                }
            }
            if (tx == 0) mbar_arrive(mb + (NSTAGE + stage) * 8);
            if (++stage == NSTAGE) { stage = 0; ph ^= 1; }
        }

        // epilogue: scale by Dl, store out
        float2 dlp[3];
        #pragma unroll
        for (int j = 0; j < 3; j++) dlp[j] = *(const float2*)&sDl[2 * tx + 64 * j];
        float* ob = out + nc * PP + w0;
        #pragma unroll
        for (int i = 0; i < 8; i++) {
            const int t = wc + 8 * i;
            #pragma unroll
            for (int j = 0; j < 3; j++) {
                float lo, hi; unpack2(acc2[i][j], lo, hi);
                float2 o; o.x = lo * dlp[j].x; o.y = hi * dlp[j].y;
                *(float2*)&ob[t * VV + 2 * tx + 64 * j] = o;
            }
        }
    }
}

// ---------------------------------------------------------------------------
extern "C" void kernel_launch(void* const* d_in, const int* in_sizes, int n_in,
                              void* d_out, int out_size) {
    const float* x      = (const float*)d_in[0];
    const float* A      = (const float*)d_in[1];
    const float* conv_w = (const float*)d_in[2];
    const float* conv_b = (const float*)d_in[3];
    const float* w1     = (const float*)d_in[4];
    const float* b1     = (const float*)d_in[5];
    const float* w2     = (const float*)d_in[6];
    const float* b2     = (const float*)d_in[7];
    const float* w3     = (const float*)d_in[8];
    const float* b3     = (const float*)d_in[9];

    float* out = (float*)d_out;
    float* An  = out + XP_ELEMS;   // tuple layout: out first, then An

    cudaFuncSetAttribute(mlp_kernel, cudaFuncAttributeMaxDynamicSharedMemorySize, S2_BYTES);
    cudaFuncSetAttribute(out_kernel, cudaFuncAttributeMaxDynamicSharedMemorySize, S3_DYN_BYTES);

    zero_colsum_kernel<<<(CS_ELEMS + 255) / 256, 256>>>();
    conv_kernel<<<dim3(PP / 64, NB), 256>>>(x, conv_w, conv_b);
    mlp_kernel<<<dim3(VV / 32, VV / 16, NB), 256, S2_BYTES>>>(A, w1, b1, w2, b2, w3, b3, An);
    out_kernel<<<dim3(VV / BW, CO, NB), 384, S3_DYN_BYTES>>>(out, An);
}

// round 5
// speedup vs baseline: 1.5867x; 1.0403x over previous
#include <cuda_runtime.h>
#include <cstdint>

#define EPS_ 0.001f

// Problem constants
#define NB   16
#define CIN  64
#define CO   64
#define TT   64
#define VV   384
#define PP   (TT*VV)          // 24576 positions per (n, channel)
#define XP_ELEMS  (NB*CO*PP)  // 25165824
#define CS_ELEMS  (NB*CO*VV)  // 393216

typedef unsigned long long ull;

// Scratch (no cudaMalloc allowed)
__device__ float g_xp[XP_ELEMS];
__device__ float g_colsum[CS_ELEMS];

// ---------------------------------------------------------------------------
// packed f32x2 helpers
// ---------------------------------------------------------------------------
__device__ __forceinline__ ull pack2(float lo, float hi) {
    ull r; asm("mov.b64 %0, {%1, %2};" : "=l"(r) : "f"(lo), "f"(hi)); return r;
}
__device__ __forceinline__ ull splat2(float v) {
    ull r; asm("mov.b64 %0, {%1, %1};" : "=l"(r) : "f"(v)); return r;
}
__device__ __forceinline__ void unpack2(ull p, float& lo, float& hi) {
    asm("mov.b64 {%0, %1}, %2;" : "=f"(lo), "=f"(hi) : "l"(p));
}
__device__ __forceinline__ ull fma2(ull a, ull b, ull c) {
    ull d; asm("fma.rn.f32x2 %0, %1, %2, %3;" : "=l"(d) : "l"(a), "l"(b), "l"(c)); return d;
}

// ---------------------------------------------------------------------------
// mbarrier helpers
// ---------------------------------------------------------------------------
__device__ __forceinline__ uint32_t smem_u32(const void* p) {
    uint32_t a;
    asm("{ .reg .u64 t; cvta.to.shared.u64 t, %1; cvt.u32.u64 %0, t; }" : "=r"(a) : "l"(p));
    return a;
}
__device__ __forceinline__ void mbar_init(uint32_t a, uint32_t cnt) {
    asm volatile("mbarrier.init.shared.b64 [%0], %1;" :: "r"(a), "r"(cnt) : "memory");
}
__device__ __forceinline__ void mbar_arrive(uint32_t a) {
    asm volatile("mbarrier.arrive.shared.b64 _, [%0];" :: "r"(a) : "memory");
}
__device__ __forceinline__ void mbar_wait(uint32_t a, uint32_t parity) {
    uint32_t done;
    asm volatile(
        "{\n\t.reg .pred p;\n\t"
        "mbarrier.try_wait.parity.shared.b64 p, [%1], %2;\n\t"
        "selp.b32 %0, 1, 0, p;\n\t}"
        : "=r"(done) : "r"(a), "r"(parity) : "memory");
    if (!done) {
        asm volatile(
            "{\n\t.reg .pred P1;\n\t"
            "WL_%=:\n\t"
            "mbarrier.try_wait.parity.shared.b64 P1, [%0], %1;\n\t"
            "@P1 bra.uni WD_%=;\n\t"
            "bra.uni WL_%=;\n\t"
            "WD_%=:\n\t}"
            :: "r"(a), "r"(parity) : "memory");
    }
}

// ---------------------------------------------------------------------------
// K0: zero the column-sum accumulator
// ---------------------------------------------------------------------------
__global__ void zero_colsum_kernel() {
    int i = blockIdx.x * blockDim.x + threadIdx.x;
    if (i < CS_ELEMS) g_colsum[i] = 0.0f;
}

// ---------------------------------------------------------------------------
// K1: x'[n,o,p] = sum_c conv_w[o,c] * x[n,c,p] + conv_b[o]
// f32x2 packed over position pairs; per-thread tile 4o x 8p; block 64o x 128p.
// ---------------------------------------------------------------------------
__global__ __launch_bounds__(256) void conv_kernel(const float* __restrict__ x,
                                                   const float* __restrict__ w,
                                                   const float* __restrict__ b) {
    __shared__ float sW[64 * 65];
    __shared__ float sX[64 * 128];
    const int n   = blockIdx.y;
    const int p0  = blockIdx.x * 128;
    const int tid = threadIdx.x;

    for (int i = tid; i < 4096; i += 256)
        sW[(i >> 6) * 65 + (i & 63)] = w[i];

    const float* xb = x + n * CIN * PP;
    #pragma unroll
    for (int r = 0; r < 8; r++) {
        int idx = tid + 256 * r;       // float4 index: c = idx>>5, p4 = idx&31
        int c = idx >> 5, p4 = idx & 31;
        ((float4*)sX)[c * 32 + p4] = *((const float4*)(xb + c * PP + p0) + p4);
    }
    __syncthreads();

    const int ob = tid >> 4;   // 0..15 -> o = ob + 16*i
    const int px = tid & 15;   // p pairs: 2*px + 32*j, j=0..3
    ull acc2[4][4];
    #pragma unroll
    for (int i = 0; i < 4; i++)
        #pragma unroll
        for (int j = 0; j < 4; j++) acc2[i][j] = 0ull;

    #pragma unroll 8
    for (int c = 0; c < 64; c++) {
        ull xv[4];
        #pragma unroll
        for (int j = 0; j < 4; j++) xv[j] = *(const ull*)&sX[c * 128 + 2 * px + 32 * j];
        ull wv[4];
        #pragma unroll
        for (int i = 0; i < 4; i++) wv[i] = splat2(sW[(ob + 16 * i) * 65 + c]);
        #pragma unroll
        for (int i = 0; i < 4; i++)
            #pragma unroll
            for (int j = 0; j < 4; j++) acc2[i][j] = fma2(wv[i], xv[j], acc2[i][j]);
    }

    #pragma unroll
    for (int i = 0; i < 4; i++) {
        int o = ob + 16 * i;
        float bo = __ldg(&b[o]);
        float* op = g_xp + (n * CO + o) * PP + p0;
        #pragma unroll
        for (int j = 0; j < 4; j++) {
            float lo, hi; unpack2(acc2[i][j], lo, hi);
            float2 o2; o2.x = lo + bo; o2.y = hi + bo;
            *(float2*)&op[2 * px + 32 * j] = o2;
        }
    }
}

// ---------------------------------------------------------------------------
// K2: MLP 7->16->32->64 (ReLU each stage), mask multiply -> Am + colsum.
// (unchanged)
// ---------------------------------------------------------------------------
#define S2_A    0
#define S2_H2   4096
#define S2_W1T  20480
#define S2_B1   20608
#define S2_W2T  20624
#define S2_B2   21136
#define S2_W3T  21168
#define S2_B3   23216
#define S2_FLOATS 23280
#define S2_BYTES  (S2_FLOATS * 4)

__global__ __launch_bounds__(256, 2) void mlp_kernel(
    const float* __restrict__ A,
    const float* __restrict__ w1, const float* __restrict__ b1,
    const float* __restrict__ w2, const float* __restrict__ b2,
    const float* __restrict__ w3, const float* __restrict__ b3,
    float* __restrict__ Am)
{
    extern __shared__ float s[];
    float* sA   = s + S2_A;
    float* sH2  = s + S2_H2;
    float* sW1t = s + S2_W1T; float* sB1 = s + S2_B1;
    float* sW2t = s + S2_W2T; float* sB2 = s + S2_B2;
    float* sW3t = s + S2_W3T; float* sB3 = s + S2_B3;

    const int tid = threadIdx.x;
    const int w0  = blockIdx.x * 32;
    const int v0  = blockIdx.y * 16;
    const int n   = blockIdx.z;

    if (tid < 112) { int c = tid / 7, k = tid % 7; sW1t[k * 16 + c] = w1[tid]; }
    if (tid < 16)  sB1[tid] = b1[tid];
    for (int i = tid; i < 512; i += 256)  { int c = i >> 4, k = i & 15; sW2t[k * 32 + c] = w2[i]; }
    if (tid < 32)  sB2[tid] = b2[tid];
    for (int i = tid; i < 2048; i += 256) { int c = i >> 5, k = i & 31; sW3t[k * 64 + c] = w3[i]; }
    if (tid < 64)  sB3[tid] = b3[tid];

    {
        const int w   = tid & 31;
        const int sub = tid >> 5;
        const float* Ab = A + n * 8 * VV * VV;
        #pragma unroll
        for (int k = 0; k < 8; k++)
            #pragma unroll
            for (int vi = 0; vi < 2; vi++) {
                int v = sub + vi * 8;
                sA[k * 512 + v * 32 + w] = Ab[(k * VV + v0 + v) * VV + w0 + w];
            }
    }
    __syncthreads();

    #pragma unroll
    for (int jj = 0; jj < 2; jj++) {
        const int p = tid + jj * 256;
        float av[7];
        #pragma unroll
        for (int k = 0; k < 7; k++) av[k] = sA[k * 512 + p];

        ull h1p[8];
        #pragma unroll
        for (int ci = 0; ci < 8; ci++) h1p[ci] = *(const ull*)&sB1[2 * ci];
        #pragma unroll
        for (int k = 0; k < 7; k++) {
            ull sv = splat2(av[k]);
            #pragma unroll
            for (int ci = 0; ci < 8; ci++)
                h1p[ci] = fma2(sv, *(const ull*)&sW1t[k * 16 + 2 * ci], h1p[ci]);
        }
        float h1[16];
        #pragma unroll
        for (int ci = 0; ci < 8; ci++) {
            float lo, hi; unpack2(h1p[ci], lo, hi);
            h1[2 * ci]     = fmaxf(lo, 0.0f);
            h1[2 * ci + 1] = fmaxf(hi, 0.0f);
        }

        ull h2p[16];
        #pragma unroll
        for (int ci = 0; ci < 16; ci++) h2p[ci] = *(const ull*)&sB2[2 * ci];
        #pragma unroll
        for (int k = 0; k < 16; k++) {
            ull sv = splat2(h1[k]);
            #pragma unroll
            for (int ci = 0; ci < 16; ci++)
                h2p[ci] = fma2(sv, *(const ull*)&sW2t[k * 32 + 2 * ci], h2p[ci]);
        }
        #pragma unroll
        for (int ci = 0; ci < 16; ci++) {
            float lo, hi; unpack2(h2p[ci], lo, hi);
            sH2[(2 * ci) * 512 + p]     = fmaxf(lo, 0.0f);
            sH2[(2 * ci + 1) * 512 + p] = fmaxf(hi, 0.0f);
        }
    }
    __syncthreads();

    {
        const int w  = tid & 31;
        const int cb = tid >> 5;
        float cs[8];
        #pragma unroll
        for (int i = 0; i < 8; i++) cs[i] = 0.0f;
        ull bp[4];
        #pragma unroll
        for (int ci = 0; ci < 4; ci++) bp[ci] = *(const ull*)&sB3[cb * 8 + 2 * ci];

        #pragma unroll
        for (int pass = 0; pass < 4; pass++) {
            ull acc2[4][4];
            #pragma unroll
            for (int ci = 0; ci < 4; ci++)
                #pragma unroll
                for (int vi = 0; vi < 4; vi++) acc2[ci][vi] = bp[ci];

            #pragma unroll 8
            for (int k = 0; k < 32; k++) {
                ull hs[4];
                #pragma unroll
                for (int vi = 0; vi < 4; vi++)
                    hs[vi] = splat2(sH2[k * 512 + (pass * 4 + vi) * 32 + w]);
                ull wv[4];
                #pragma unroll
                for (int ci = 0; ci < 4; ci++)
                    wv[ci] = *(const ull*)&sW3t[k * 64 + cb * 8 + 2 * ci];
                #pragma unroll
                for (int ci = 0; ci < 4; ci++)
                    #pragma unroll
                    for (int vi = 0; vi < 4; vi++)
                        acc2[ci][vi] = fma2(hs[vi], wv[ci], acc2[ci][vi]);
            }

            #pragma unroll
            for (int vi = 0; vi < 4; vi++) {
                const int v = pass * 4 + vi;
                float m = sA[7 * 512 + v * 32 + w];
                #pragma unroll
                for (int ci = 0; ci < 4; ci++) {
                    float lo, hi; unpack2(acc2[ci][vi], lo, hi);
                    float a0 = fmaxf(lo, 0.0f) * m;
                    float a1 = fmaxf(hi, 0.0f) * m;
                    int c0 = cb * 8 + 2 * ci;
                    Am[((n * CO + c0)     * VV + (v0 + v)) * VV + w0 + w] = a0;
                    Am[((n * CO + c0 + 1) * VV + (v0 + v)) * VV + w0 + w] = a1;
                    cs[2 * ci]     += a0;
                    cs[2 * ci + 1] += a1;
                }
            }
        }
        #pragma unroll
        for (int i = 0; i < 8; i++)
            atomicAdd(&g_colsum[(n * CO + cb * 8 + i) * VV + w0 + w], cs[i]);
    }
}

// ---------------------------------------------------------------------------
// K3: warp-specialized, fully chunked streaming (both An AND x' chunks flow
// through a 3-stage smem ring) -> 72KB smem, 2 blocks/SM, 24 warps/SM.
// Block = (n, c, 128-wide w tile), 384 threads:
//   warps 0..7  consumers: GEMM out[t,w] = Dl[w] * sum_v x'[t,v]*Am[v,w]
//   warps 8..11 producers: stream Am + x' chunks, write normalized An.
// ---------------------------------------------------------------------------
#define BW      128
#define CHUNK_V 32
#define NSTAGE  3
#define STA_FLOATS (CHUNK_V * BW)          // 4096  (An stage)
#define STX_FLOATS (TT * CHUNK_V)          // 2048  (X stage)
#define S3_XOFF    (NSTAGE * STA_FLOATS)   // 12288
#define S3_DYN_FLOATS (NSTAGE * (STA_FLOATS + STX_FLOATS))   // 18432
#define S3_DYN_BYTES  (S3_DYN_FLOATS * 4)                     // 73728

__global__ __launch_bounds__(384, 2) void out_kernel(float* __restrict__ out,
                                                     float* __restrict__ An)
{
    extern __shared__ float s[];
    float* sAn = s;                 // [3][32][128]
    float* sXc = s + S3_XOFF;       // [3][64][32]
    __shared__ float sDl[BW];
    __shared__ __align__(8) ull s_mbar[2 * NSTAGE];

    const int tid = threadIdx.x;
    const int w0  = blockIdx.x * BW;
    const int c   = blockIdx.y;
    const int n   = blockIdx.z;
    const int nc  = n * CO + c;

    const uint32_t mb = smem_u32(s_mbar);
    if (tid == 0) {
        #pragma unroll
        for (int st = 0; st < NSTAGE; st++) {
            mbar_init(mb + st * 8, 128);               // full: 128 producer threads
            mbar_init(mb + (NSTAGE + st) * 8, 8);      // empty: 8 consumer warps
        }
    }
    if (tid < BW) {
        float csv = g_colsum[nc * VV + w0 + tid];
        sDl[tid] = 1.0f / (csv + EPS_);
    }
    __syncthreads();

    float* Anb = An + nc * VV * VV + w0;
    const float* Xb = g_xp + nc * PP;
    const int wid = tid >> 5;

    if (wid >= 8) {
        // ----------------- PRODUCERS (4 warps, 128 threads) -----------------
        const int ptid = tid - 256;   // 0..127
        // An: 8 float4/thread;  X: 4 float4/thread
        int stage = 0, ph = 1;
        for (int kc = 0; kc < 12; kc++) {
            float4 curA[8];
            #pragma unroll
            for (int q = 0; q < 8; q++) {
                int idx = ptid + 128 * q;       // 0..1023
                int row = idx >> 5, c4 = idx & 31;
                curA[q] = *((const float4*)(Anb + (kc * CHUNK_V + row) * VV) + c4);
            }
            float4 curX[4];
            #pragma unroll
            for (int q = 0; q < 4; q++) {
                int idx = ptid + 128 * q;       // 0..511
                int t = idx >> 3, c4 = idx & 7;
                curX[q] = *((const float4*)(Xb + t * VV + kc * CHUNK_V) + c4);
            }
            mbar_wait(mb + (NSTAGE + stage) * 8, ph);
            float* bufA = sAn + stage * STA_FLOATS;
            float* bufX = sXc + stage * STX_FLOATS;
            #pragma unroll
            for (int q = 0; q < 8; q++) {
                int idx = ptid + 128 * q;
                int row = idx >> 5, c4 = idx & 31;
                ((float4*)bufA)[row * 32 + c4] = curA[q];
                const float4 d4 = ((const float4*)sDl)[c4];
                float4 o4;
                o4.x = curA[q].x * d4.x; o4.y = curA[q].y * d4.y;
                o4.z = curA[q].z * d4.z; o4.w = curA[q].w * d4.w;
                *((float4*)(Anb + (kc * CHUNK_V + row) * VV) + c4) = o4;
            }
            #pragma unroll
            for (int q = 0; q < 4; q++) {
                int idx = ptid + 128 * q;
                int t = idx >> 3, c4 = idx & 7;
                ((float4*)bufX)[t * 8 + c4] = curX[q];
            }
            mbar_arrive(mb + stage * 8);
            if (++stage == NSTAGE) { stage = 0; ph ^= 1; }
        }
    } else {
        // ----------------- CONSUMERS (8 warps, 256 threads) -----------------
        const int tx = tid & 31;      // w pairs: 2*tx + 64*j (j=0,1)
        const int wc = wid;           // t rows: wc + 8*i (i=0..7)
        ull acc2[8][2];
        #pragma unroll
        for (int i = 0; i < 8; i++) { acc2[i][0] = 0ull; acc2[i][1] = 0ull; }

        int stage = 0, ph = 0;
        for (int kc = 0; kc < 12; kc++) {
            mbar_wait(mb + stage * 8, ph);
            const float* bufA = sAn + stage * STA_FLOATS;
            const float* bufX = sXc + stage * STX_FLOATS;
            #pragma unroll
            for (int v4 = 0; v4 < 8; v4++) {
                #pragma unroll
                for (int half = 0; half < 2; half++) {
                    float4 xq[4];
                    #pragma unroll
                    for (int ii = 0; ii < 4; ii++)
                        xq[ii] = *(const float4*)&bufX[(wc + 8 * (half * 4 + ii)) * CHUNK_V + v4 * 4];
                    #pragma unroll
                    for (int vv = 0; vv < 4; vv++) {
                        ull av0 = *(const ull*)&bufA[(v4 * 4 + vv) * BW + 2 * tx];
                        ull av1 = *(const ull*)&bufA[(v4 * 4 + vv) * BW + 2 * tx + 64];
                        #pragma unroll
                        for (int ii = 0; ii < 4; ii++) {
                            float xs = (vv == 0) ? xq[ii].x : (vv == 1) ? xq[ii].y
                                     : (vv == 2) ? xq[ii].z : xq[ii].w;
                            ull sv = splat2(xs);
                            const int i = half * 4 + ii;
                            acc2[i][0] = fma2(sv, av0, acc2[i][0]);
                            acc2[i][1] = fma2(sv, av1, acc2[i][1]);
                        }
                    }
                }
            }
            if (tx == 0) mbar_arrive(mb + (NSTAGE + stage) * 8);
            if (++stage == NSTAGE) { stage = 0; ph ^= 1; }
        }

        // epilogue: scale by Dl, store out
        float2 dlp[2];
        #pragma unroll
        for (int j = 0; j < 2; j++) dlp[j] = *(const float2*)&sDl[2 * tx + 64 * j];
        float* ob = out + nc * PP + w0;
        #pragma unroll
        for (int i = 0; i < 8; i++) {
            const int t = wc + 8 * i;
            #pragma unroll
            for (int j = 0; j < 2; j++) {
                float lo, hi; unpack2(acc2[i][j], lo, hi);
                float2 o; o.x = lo * dlp[j].x; o.y = hi * dlp[j].y;
                *(float2*)&ob[t * VV + 2 * tx + 64 * j] = o;
            }
        }
    }
}

// ---------------------------------------------------------------------------
extern "C" void kernel_launch(void* const* d_in, const int* in_sizes, int n_in,
                              void* d_out, int out_size) {
    const float* x      = (const float*)d_in[0];
    const float* A      = (const float*)d_in[1];
    const float* conv_w = (const float*)d_in[2];
    const float* conv_b = (const float*)d_in[3];
    const float* w1     = (const float*)d_in[4];
    const float* b1     = (const float*)d_in[5];
    const float* w2     = (const float*)d_in[6];
    const float* b2     = (const float*)d_in[7];
    const float* w3     = (const float*)d_in[8];
    const float* b3     = (const float*)d_in[9];

    float* out = (float*)d_out;
    float* An  = out + XP_ELEMS;   // tuple layout: out first, then An

    cudaFuncSetAttribute(mlp_kernel, cudaFuncAttributeMaxDynamicSharedMemorySize, S2_BYTES);
    cudaFuncSetAttribute(out_kernel, cudaFuncAttributeMaxDynamicSharedMemorySize, S3_DYN_BYTES);

    zero_colsum_kernel<<<(CS_ELEMS + 255) / 256, 256>>>();
    conv_kernel<<<dim3(PP / 128, NB), 256>>>(x, conv_w, conv_b);
    mlp_kernel<<<dim3(VV / 32, VV / 16, NB), 256, S2_BYTES>>>(A, w1, b1, w2, b2, w3, b3, An);
    out_kernel<<<dim3(VV / BW, CO, NB), 384, S3_DYN_BYTES>>>(out, An);
}